// round 16
// baseline (speedup 1.0000x reference)
#include <cuda_runtime.h>
#include <cuda_bf16.h>
#include <math.h>
#include <stdint.h>

#define BB 4
#define C 512
#define HS 32
#define H2 64
#define SLAB_ROWS 4356           /* 66x66 padded pixel grid */
#define NSTAGES 72               /* 3 dy x 3 dx x 8 cig */
#define STAGE_B 98304            /* Ah16K + Al16K + Bh32K + Bl32K */
#define OFF_SCAL 196608
#define SM_GEMM 200704           /* 2 stages + 4KB scalars */
#define B_LAYER_OFF ((size_t)72 * 512 * 128)

// ---------------- scratch ----------------
__device__ float g_s0[BB * C];
__device__ float g_s1[BB * C];
__device__ float g_sr[BB * C];
__device__ float g_d0[BB * C];
__device__ float g_d1[BB * C];
__device__ float g_Q[2 * C * C];
__device__ float g_x0[(size_t)BB * C * H2 * H2];
__device__ __align__(1024) unsigned char g_Ah[(size_t)BB * 8 * SLAB_ROWS * 128];
__device__ __align__(1024) unsigned char g_Al[(size_t)BB * 8 * SLAB_ROWS * 128];
__device__ __align__(1024) unsigned char g_Ah2[(size_t)BB * 8 * SLAB_ROWS * 128];
__device__ __align__(1024) unsigned char g_Al2[(size_t)BB * 8 * SLAB_ROWS * 128];
__device__ __align__(1024) unsigned char g_Bh[(size_t)2 * 72 * 512 * 128];
__device__ __align__(1024) unsigned char g_Bl[(size_t)2 * 72 * 512 * 128];

__device__ __forceinline__ float conv_scale() {
    return 1.3867504905630728f / 67.88225099390857f;
}
__device__ __forceinline__ float ms_scale() { return 0.04419417382415922f; }
__device__ __forceinline__ float rgb_scale() {
    return 1.3867504905630728f * 0.06231769651245859f;
}

// ---------------- PTX helpers (baseline ISA) ----------------
__device__ __forceinline__ uint32_t smem_u32(const void* p) {
    uint32_t a;
    asm("{ .reg .u64 t; cvta.to.shared.u64 t, %1; cvt.u32.u64 %0, t; }" : "=r"(a) : "l"(p));
    return a;
}
#define CP_ASYNC16(dst, src) \
    asm volatile("cp.async.cg.shared.global [%0], [%1], 16;" :: "r"(dst), "l"(src))
#define CP_COMMIT() asm volatile("cp.async.commit_group;" ::: "memory")
#define CP_WAIT1() asm volatile("cp.async.wait_group 1;" ::: "memory")
#define CP_WAIT0() asm volatile("cp.async.wait_group 0;" ::: "memory")

__device__ __forceinline__ void ldsm4(uint32_t* r, uint32_t addr) {
    asm volatile("ldmatrix.sync.aligned.m8n8.x4.shared.b16 {%0,%1,%2,%3}, [%4];"
        : "=r"(r[0]), "=r"(r[1]), "=r"(r[2]), "=r"(r[3]) : "r"(addr));
}
__device__ __forceinline__ void mma_bf16(float* c, const uint32_t* a,
                                         uint32_t b0, uint32_t b1) {
    asm volatile("mma.sync.aligned.m16n8k16.row.col.f32.bf16.bf16.f32 "
        "{%0,%1,%2,%3}, {%4,%5,%6,%7}, {%8,%9}, {%0,%1,%2,%3};"
        : "+f"(c[0]), "+f"(c[1]), "+f"(c[2]), "+f"(c[3])
        : "r"(a[0]), "r"(a[1]), "r"(a[2]), "r"(a[3]), "r"(b0), "r"(b1));
}
__device__ __forceinline__ uint32_t pack_bf16(float v0, float v1) {
    __nv_bfloat16 h0 = __float2bfloat16(v0);
    __nv_bfloat16 h1 = __float2bfloat16(v1);
    return (uint32_t)*(unsigned short*)&h0 | ((uint32_t)*(unsigned short*)&h1 << 16);
}
__device__ __forceinline__ float bf16_lo_res(float v) {
    __nv_bfloat16 h = __float2bfloat16(v);
    return v - __bfloat162float(h);
}

// ---------------- styles ----------------
__global__ void styles_kernel(const float* __restrict__ w,
                              const float* __restrict__ ms0_w, const float* __restrict__ ms0_b,
                              const float* __restrict__ ms1_w, const float* __restrict__ ms1_b,
                              const float* __restrict__ msr_w, const float* __restrict__ msr_b)
{
    int gw = (blockIdx.x * blockDim.x + threadIdx.x) >> 5;
    int lane = threadIdx.x & 31;
    if (gw >= 3 * BB * C) return;
    int which = gw / (BB * C);
    int rem = gw % (BB * C);
    int b = rem / C;
    int i = rem % C;
    const float* msw = which == 0 ? ms0_w : which == 1 ? ms1_w : msr_w;
    const float* msb = which == 0 ? ms0_b : which == 1 ? ms1_b : msr_b;
    const float* wr = w + b * C;
    const float* mr = msw + i * C;
    float acc = 0.f;
    for (int j = lane; j < C; j += 32) acc += wr[j] * mr[j];
#pragma unroll
    for (int o = 16; o; o >>= 1) acc += __shfl_xor_sync(0xffffffffu, acc, o);
    if (lane == 0) {
        float s = acc * ms_scale() + msb[i];
        (which == 0 ? g_s0 : which == 1 ? g_s1 : g_sr)[b * C + i] = s;
    }
}

__global__ void q_kernel(const float* __restrict__ w0, const float* __restrict__ w1)
{
    int idx = blockIdx.x * blockDim.x + threadIdx.x;
    if (idx >= 2 * C * C) return;
    const float* W = idx < C * C ? w0 : w1;
    int e = idx < C * C ? idx : idx - C * C;
    const float* p = W + (size_t)e * 9;
    float s = 0.f;
#pragma unroll
    for (int t = 0; t < 9; t++) s += p[t] * p[t];
    float cs = conv_scale();
    g_Q[idx] = s * cs * cs;
}

__global__ void demod_kernel()
{
    int gw = (blockIdx.x * blockDim.x + threadIdx.x) >> 5;
    int lane = threadIdx.x & 31;
    if (gw >= 2 * BB * C) return;
    int layer = gw / (BB * C);
    int rem = gw % (BB * C);
    int b = rem / C;
    int co = rem % C;
    const float* Q = g_Q + (size_t)layer * C * C + (size_t)co * C;
    const float* s = (layer ? g_s1 : g_s0) + b * C;
    float acc = 0.f;
    for (int ci = lane; ci < C; ci += 32) { float sv = s[ci]; acc += Q[ci] * sv * sv; }
#pragma unroll
    for (int o = 16; o; o >>= 1) acc += __shfl_xor_sync(0xffffffffu, acc, o);
    if (lane == 0) (layer ? g_d1 : g_d0)[b * C + co] = rsqrtf(acc + 1e-8f);
}

__global__ void upsample_scale_kernel(const float* __restrict__ maps)
{
    int idx = blockIdx.x * blockDim.x + threadIdx.x;
    if (idx >= BB * C * H2 * H2) return;
    int x = idx & 63;
    int y = (idx >> 6) & 63;
    int c = (idx >> 12) & (C - 1);
    int b = idx >> 21;
    float sy = 0.5f * y - 0.25f;
    float sx = 0.5f * x - 0.25f;
    int yi = (int)floorf(sy);
    int xi = (int)floorf(sx);
    float wy = sy - yi;
    float wx = sx - xi;
    int ya = yi < 0 ? 0 : yi;
    int yb = yi + 1 > HS - 1 ? HS - 1 : yi + 1;
    int xa = xi < 0 ? 0 : xi;
    int xb = xi + 1 > HS - 1 ? HS - 1 : xi + 1;
    const float* m = maps + ((size_t)b * C + c) * HS * HS;
    float v = (1.f - wy) * ((1.f - wx) * m[ya * HS + xa] + wx * m[ya * HS + xb]) +
              wy * ((1.f - wx) * m[yb * HS + xa] + wx * m[yb * HS + xb]);
    g_x0[idx] = v * g_s0[b * C + c];
}

// ---------------- zero padded-border rows of A slabs --------------
__global__ void zero_pad_kernel(unsigned char* __restrict__ Ah, unsigned char* __restrict__ Al)
{
    int i = blockIdx.x * 256 + threadIdx.x;   // 32 slabs * 260 rows * 8 chunks
    if (i >= 32 * 260 * 8) return;
    int ch = i & 7;
    int t = i >> 3;
    int slab = t / 260;
    int rr = t % 260;
    int r;
    if (rr < 66) r = rr;
    else if (rr < 132) r = 4290 + (rr - 66);
    else if (rr < 196) r = (rr - 132 + 1) * 66;
    else r = (rr - 196 + 1) * 66 + 65;
    size_t off = ((size_t)slab * SLAB_ROWS + r) * 128 + ch * 16;
    uint4 z = make_uint4(0u, 0u, 0u, 0u);
    *(uint4*)(Ah + off) = z;
    *(uint4*)(Al + off) = z;
}

// ---------------- prep A: x[b][ci][y][x] -> padded bf16 hi/lo -----
__global__ __launch_bounds__(256)
void prep_A_kernel(const float* __restrict__ x)
{
    __shared__ float tile[64][65];
    const int y = blockIdx.x;
    const int cig = blockIdx.y;
    const int b = blockIdx.z;
    const int tid = threadIdx.x;
    const float* xp = x + ((size_t)(b * C + cig * 64) * 64 + y) * 64;
    for (int i = tid; i < 4096; i += 256)
        tile[i >> 6][i & 63] = xp[(size_t)(i >> 6) * 4096 + (i & 63)];
    __syncthreads();
    const int xo = tid >> 2;
    const int q = tid & 3;
    uint32_t hh[8], ll[8];
#pragma unroll
    for (int k = 0; k < 8; k++) {
        float v0 = tile[q * 16 + 2 * k][xo];
        float v1 = tile[q * 16 + 2 * k + 1][xo];
        hh[k] = pack_bf16(v0, v1);
        ll[k] = pack_bf16(bf16_lo_res(v0), bf16_lo_res(v1));
    }
    size_t r = (size_t)(y + 1) * 66 + xo + 1;
    size_t base = (((size_t)(b * 8 + cig)) * SLAB_ROWS + r) * 128 + q * 32;
    *(uint4*)(g_Ah + base)      = make_uint4(hh[0], hh[1], hh[2], hh[3]);
    *(uint4*)(g_Ah + base + 16) = make_uint4(hh[4], hh[5], hh[6], hh[7]);
    *(uint4*)(g_Al + base)      = make_uint4(ll[0], ll[1], ll[2], ll[3]);
    *(uint4*)(g_Al + base + 16) = make_uint4(ll[4], ll[5], ll[6], ll[7]);
}

// ---------------- prep B ----------------
__global__ void prep_B_kernel(const float* __restrict__ w0, const float* __restrict__ w1)
{
    int idx = blockIdx.x * 256 + threadIdx.x;
    if (idx >= 589824) return;
    int g = idx & 7;
    int t = idx >> 3;
    int co = t & 511; t >>= 9;
    int cig = t & 7; t >>= 3;
    int dx = t % 3; t /= 3;
    int dy = t % 3;
    int layer = t / 3;
    const float* W = layer ? w1 : w0;
    const float cs = conv_scale();
    uint32_t hh[4], ll[4];
#pragma unroll
    for (int k = 0; k < 4; k++) {
        int ci0 = cig * 64 + g * 8 + 2 * k;
        float v0 = W[(((size_t)co * C + ci0) * 3 + dy) * 3 + dx] * cs;
        float v1 = W[(((size_t)co * C + ci0 + 1) * 3 + dy) * 3 + dx] * cs;
        hh[k] = pack_bf16(v0, v1);
        ll[k] = pack_bf16(bf16_lo_res(v0), bf16_lo_res(v1));
    }
    size_t off = ((size_t)(((layer * 3 + dy) * 3 + dx) * 8 + cig) * 512 + co) * 128 + g * 16;
    *(uint4*)(g_Bh + off) = make_uint4(hh[0], hh[1], hh[2], hh[3]);
    *(uint4*)(g_Bl + off) = make_uint4(ll[0], ll[1], ll[2], ll[3]);
}

// ---------------- HMMA conv GEMM ----------------------------------
// CTA 128 px x 256 co, 16 warps (2m x 8n), warp 64x32. 72 merged stages.
// Epilogue math folded into transpose; output either tensor or bf16 slabs.
__global__ __launch_bounds__(512, 1)
void hgemm_conv_kernel(const unsigned char* __restrict__ Ah, const unsigned char* __restrict__ Al,
                       const unsigned char* __restrict__ Bh, const unsigned char* __restrict__ Bl,
                       const float* __restrict__ dmod, const float* __restrict__ bias,
                       const float* __restrict__ ns, const float* __restrict__ noise,
                       const float* __restrict__ snext,
                       unsigned char* __restrict__ slab_h, unsigned char* __restrict__ slab_l,
                       float* __restrict__ out)
{
    extern __shared__ unsigned char sm[];
    const uint32_t sb = smem_u32(sm);
    const int tid = threadIdx.x;
    const int wid = tid >> 5;
    const int lane = tid & 31;
    const int tm = blockIdx.x;    // 0..31 (2 output rows)
    const int nb = blockIdx.y;    // 0..1 (co half)
    const int b = blockIdx.z;
    const int wm = wid >> 3;      // 0..1
    const int wn = wid & 7;       // 0..7

    // epilogue scalars (region outside stage ring)
    float* dvv = (float*)(sm + OFF_SCAL);
    float* bvv = dvv + 256;
    float* nvv = bvv + 256;
    float* svv = nvv + 256;
    for (int i = tid; i < 256; i += 512) {
        int cog = nb * 256 + i;
        dvv[i] = dmod[b * C + cog];
        bvv[i] = bias[cog];
        nvv[i] = ns[cog];
        svv[i] = snext ? snext[b * C + cog] : 1.f;
    }

    auto load_stage = [&](int s) {
        int dy = s / 24, r2 = s % 24, dx = r2 / 8, cig = r2 % 8;
        const unsigned char* gAh = Ah + ((size_t)(b * 8 + cig) * SLAB_ROWS) * 128;
        const unsigned char* gAl = Al + ((size_t)(b * 8 + cig) * SLAB_ROWS) * 128;
        const size_t boff = ((size_t)((dy * 3 + dx) * 8 + cig) * 512 + nb * 256) * 128;
        const unsigned char* gBh = Bh + boff;
        const unsigned char* gBl = Bl + boff;
        const int seg0 = (2 * tm + dy) * 66 + dx;
        uint32_t buf = sb + (uint32_t)(s & 1) * STAGE_B;
#pragma unroll
        for (int i = 0; i < 2; i++) {
            int id = tid + i * 512;
            int row = id >> 3, cc = id & 7;
            int grow = seg0 + row + ((row >= 64) ? 2 : 0);
            uint32_t sw = (uint32_t)(cc ^ (row & 7)) << 4;
            CP_ASYNC16(buf + ((uint32_t)row << 7) + sw, gAh + ((size_t)grow << 7) + (cc << 4));
            CP_ASYNC16(buf + 16384u + ((uint32_t)row << 7) + sw, gAl + ((size_t)grow << 7) + (cc << 4));
        }
#pragma unroll
        for (int i = 0; i < 4; i++) {
            int id = tid + i * 512;
            int row = id >> 3, cc = id & 7;
            uint32_t sw = (uint32_t)(cc ^ (row & 7)) << 4;
            CP_ASYNC16(buf + 32768u + ((uint32_t)row << 7) + sw, gBh + ((size_t)id << 4));
            CP_ASYNC16(buf + 65536u + ((uint32_t)row << 7) + sw, gBl + ((size_t)id << 4));
        }
    };

    float acc[4][4][4];
#pragma unroll
    for (int mi = 0; mi < 4; mi++)
#pragma unroll
        for (int nj = 0; nj < 4; nj++)
#pragma unroll
            for (int q = 0; q < 4; q++) acc[mi][nj][q] = 0.f;

    load_stage(0); CP_COMMIT();

#pragma unroll 1
    for (int s = 0; s < NSTAGES; s++) {
        if (s + 1 < NSTAGES) { load_stage(s + 1); CP_COMMIT(); CP_WAIT1(); }
        else CP_WAIT0();
        __syncthreads();
        const uint32_t st = sb + (uint32_t)(s & 1) * STAGE_B;
#pragma unroll
        for (int ks = 0; ks < 4; ks++) {
            const int c = ks * 2 + (lane >> 4);
            const int lr = lane & 15;
            uint32_t bh[2][4];
#pragma unroll
            for (int bq = 0; bq < 2; bq++) {
                int n = wn * 32 + bq * 16 + lr;
                uint32_t off = ((uint32_t)n << 7) + ((uint32_t)(c ^ (n & 7)) << 4);
                ldsm4(bh[bq], st + 32768u + off);
            }
            uint32_t ah[4][4];
#pragma unroll
            for (int mi = 0; mi < 4; mi++) {
                int m = wm * 64 + mi * 16 + lr;
                uint32_t off = ((uint32_t)m << 7) + ((uint32_t)(c ^ (m & 7)) << 4);
                ldsm4(ah[mi], st + off);
                uint32_t al[4];
                ldsm4(al, st + 16384u + off);
#pragma unroll
                for (int nj = 0; nj < 4; nj++)
                    mma_bf16(acc[mi][nj], ah[mi], bh[nj >> 1][nj & 1], bh[nj >> 1][(nj & 1) + 2]);
#pragma unroll
                for (int nj = 0; nj < 4; nj++)
                    mma_bf16(acc[mi][nj], al, bh[nj >> 1][nj & 1], bh[nj >> 1][(nj & 1) + 2]);
            }
#pragma unroll
            for (int bq = 0; bq < 2; bq++) {
                int n = wn * 32 + bq * 16 + lr;
                uint32_t off = ((uint32_t)n << 7) + ((uint32_t)(c ^ (n & 7)) << 4);
                ldsm4(bh[bq], st + 65536u + off);   // Bl overwrites
            }
#pragma unroll
            for (int mi = 0; mi < 4; mi++)
#pragma unroll
                for (int nj = 0; nj < 4; nj++)
                    mma_bf16(acc[mi][nj], ah[mi], bh[nj >> 1][nj & 1], bh[nj >> 1][(nj & 1) + 2]);
        }
        __syncthreads();
    }

    // transpose with fused epilogue math -> T holds FINAL values
    float* T = (float*)sm;   // [256 co][132]
    {
        const float* noi = noise + ((size_t)b * 64 + 2 * tm + wm) * 64;
#pragma unroll
        for (int mi = 0; mi < 4; mi++) {
            const int xr = mi * 16 + (lane >> 2);
            const float n0 = noi[xr];
            const float n1 = noi[xr + 8];
            const int mrow = wm * 64 + xr;
#pragma unroll
            for (int nj = 0; nj < 4; nj++) {
                const int nc = wn * 32 + nj * 8 + (lane & 3) * 2;
                float v;
                v = acc[mi][nj][0] * dvv[nc] + bvv[nc] + nvv[nc] * n0;
                v = v >= 0.f ? v : 0.2f * v;
                T[nc * 132 + mrow] = v * svv[nc];
                v = acc[mi][nj][1] * dvv[nc + 1] + bvv[nc + 1] + nvv[nc + 1] * n0;
                v = v >= 0.f ? v : 0.2f * v;
                T[(nc + 1) * 132 + mrow] = v * svv[nc + 1];
                v = acc[mi][nj][2] * dvv[nc] + bvv[nc] + nvv[nc] * n1;
                v = v >= 0.f ? v : 0.2f * v;
                T[nc * 132 + mrow + 8] = v * svv[nc];
                v = acc[mi][nj][3] * dvv[nc + 1] + bvv[nc + 1] + nvv[nc + 1] * n1;
                v = v >= 0.f ? v : 0.2f * v;
                T[(nc + 1) * 132 + mrow + 8] = v * svv[nc + 1];
            }
        }
    }
    __syncthreads();

    if (slab_h) {
        // write layer-1 A slabs directly: bf16 hi/lo, padded 66x66 grid
#pragma unroll
        for (int k = 0; k < 4; k++) {
            int it = tid + k * 512;          // 0..2047
            int half = it >> 10;
            int rem = it & 1023;
            int x = rem & 63;
            int q = (rem >> 6) & 3;
            int cig = rem >> 8;
            const float* tp = T + (cig * 64 + q * 16) * 132 + half * 64 + x;
            uint32_t hh[8], ll[8];
#pragma unroll
            for (int j = 0; j < 8; j++) {
                float v0 = tp[(2 * j) * 132];
                float v1 = tp[(2 * j + 1) * 132];
                hh[j] = pack_bf16(v0, v1);
                ll[j] = pack_bf16(bf16_lo_res(v0), bf16_lo_res(v1));
            }
            size_t r = (size_t)(2 * tm + half + 1) * 66 + x + 1;
            size_t off = (((size_t)(b * 8 + nb * 4 + cig)) * SLAB_ROWS + r) * 128 + q * 32;
            *(uint4*)(slab_h + off)      = make_uint4(hh[0], hh[1], hh[2], hh[3]);
            *(uint4*)(slab_h + off + 16) = make_uint4(hh[4], hh[5], hh[6], hh[7]);
            *(uint4*)(slab_l + off)      = make_uint4(ll[0], ll[1], ll[2], ll[3]);
            *(uint4*)(slab_l + off + 16) = make_uint4(ll[4], ll[5], ll[6], ll[7]);
        }
    } else {
        const int co = tid & 255;
        const int half = tid >> 8;
        const int cog = nb * 256 + co;
        const int y = 2 * tm + half;
        float* op = out + ((size_t)(b * C + cog) * 64 + y) * 64;
        const float* tr = T + co * 132 + half * 64;
#pragma unroll
        for (int x4 = 0; x4 < 16; x4++)
            *(float4*)(op + x4 * 4) = *(const float4*)(tr + x4 * 4);
    }
}

// ---------------- to_rgb ------------------------------------------
__global__ void rgb_kernel(const float* __restrict__ rgb_in, const float* __restrict__ rgb_w,
                           const float* __restrict__ rgb_b, const float* __restrict__ h,
                           float* __restrict__ out)
{
    __shared__ float coef[3 * C];
    __shared__ float part[4][3][64];
    int b = blockIdx.x >> 6;
    int y = blockIdx.x & 63;
    int tid = threadIdx.x;
    const float rs = rgb_scale();
    for (int i = tid; i < 3 * C; i += 256) {
        int c2 = i >> 9;
        int co = i & (C - 1);
        coef[i] = rgb_w[c2 * C + co] * rs * g_sr[b * C + co];
    }
    __syncthreads();
    int px = tid & 63;
    int cg = tid >> 6;
    float a0 = 0.f, a1 = 0.f, a2 = 0.f;
    const float* hp = h + (((size_t)b * C + cg * 128) * 64 + y) * 64 + px;
    const float* c0 = coef + cg * 128;
    for (int co = 0; co < 128; co++) {
        float hv = hp[(size_t)co * 4096];
        a0 += c0[co] * hv;
        a1 += c0[C + co] * hv;
        a2 += c0[2 * C + co] * hv;
    }
    part[cg][0][px] = a0;
    part[cg][1][px] = a1;
    part[cg][2][px] = a2;
    __syncthreads();
    if (tid < 192) {
        int c2 = tid / 64;
        int x = tid % 64;
        float s = part[0][c2][x] + part[1][c2][x] + part[2][c2][x] + part[3][c2][x];
        float sy = 0.5f * y - 0.25f;
        float sx = 0.5f * x - 0.25f;
        int yi = (int)floorf(sy);
        int xi = (int)floorf(sx);
        float wy = sy - yi;
        float wx = sx - xi;
        int ya = yi < 0 ? 0 : yi;
        int yb = yi + 1 > HS - 1 ? HS - 1 : yi + 1;
        int xa = xi < 0 ? 0 : xi;
        int xb2 = xi + 1 > HS - 1 ? HS - 1 : xi + 1;
        const float* rp = rgb_in + ((size_t)b * 3 + c2) * HS * HS;
        float up = (1.f - wy) * ((1.f - wx) * rp[ya * HS + xa] + wx * rp[ya * HS + xb2]) +
                   wy * ((1.f - wx) * rp[yb * HS + xa] + wx * rp[yb * HS + xb2]);
        out[(((size_t)b * 3 + c2) * 64 + y) * 64 + x] = up + rgb_b[c2] + s;
    }
}

// ---------------- launch ------------------------------------------
extern "C" void kernel_launch(void* const* d_in, const int* in_sizes, int n_in,
                              void* d_out, int out_size)
{
    const float* maps    = (const float*)d_in[0];
    const float* w       = (const float*)d_in[1];
    const float* rgb     = (const float*)d_in[2];
    const float* noise0  = (const float*)d_in[3];
    const float* noise1  = (const float*)d_in[4];
    const float* conv0_w = (const float*)d_in[5];
    const float* conv0_b = (const float*)d_in[6];
    const float* ms0_w   = (const float*)d_in[7];
    const float* ms0_b   = (const float*)d_in[8];
    const float* ns0     = (const float*)d_in[9];
    const float* conv1_w = (const float*)d_in[10];
    const float* conv1_b = (const float*)d_in[11];
    const float* ms1_w   = (const float*)d_in[12];
    const float* ms1_b   = (const float*)d_in[13];
    const float* ns1     = (const float*)d_in[14];
    const float* rgb_w   = (const float*)d_in[15];
    const float* rgb_b   = (const float*)d_in[16];
    const float* msr_w   = (const float*)d_in[17];
    const float* msr_b   = (const float*)d_in[18];

    float* out = (float*)d_out;
    float* out_rgb = out;
    float* out_h   = out + 4 * 3 * 64 * 64;

    float *px0, *pd0, *pd1, *ps1;
    unsigned char *pAh, *pAl, *pAh2, *pAl2, *pBh, *pBl;
    cudaGetSymbolAddress((void**)&px0, g_x0);
    cudaGetSymbolAddress((void**)&pd0, g_d0);
    cudaGetSymbolAddress((void**)&pd1, g_d1);
    cudaGetSymbolAddress((void**)&ps1, g_s1);
    cudaGetSymbolAddress((void**)&pAh, g_Ah);
    cudaGetSymbolAddress((void**)&pAl, g_Al);
    cudaGetSymbolAddress((void**)&pAh2, g_Ah2);
    cudaGetSymbolAddress((void**)&pAl2, g_Al2);
    cudaGetSymbolAddress((void**)&pBh, g_Bh);
    cudaGetSymbolAddress((void**)&pBl, g_Bl);

    cudaFuncSetAttribute(hgemm_conv_kernel,
                         cudaFuncAttributeMaxDynamicSharedMemorySize, SM_GEMM);

    styles_kernel<<<768, 256>>>(w, ms0_w, ms0_b, ms1_w, ms1_b, msr_w, msr_b);
    q_kernel<<<(2 * C * C + 255) / 256, 256>>>(conv0_w, conv1_w);
    demod_kernel<<<(2 * BB * C * 32 + 255) / 256, 256>>>();
    upsample_scale_kernel<<<(BB * C * H2 * H2) / 256, 256>>>(maps);
    prep_B_kernel<<<2304, 256>>>(conv0_w, conv1_w);
    zero_pad_kernel<<<260, 256>>>(pAh, pAl);
    zero_pad_kernel<<<260, 256>>>(pAh2, pAl2);

    prep_A_kernel<<<dim3(64, 8, BB), 256>>>(px0);

    // layer 0: GEMM -> writes layer-1 bf16 slabs directly
    hgemm_conv_kernel<<<dim3(32, 2, BB), 512, SM_GEMM>>>(
        pAh, pAl, pBh, pBl, pd0, conv0_b, ns0, noise0, ps1,
        pAh2, pAl2, nullptr);

    // layer 1: GEMM -> out_h tensor
    hgemm_conv_kernel<<<dim3(32, 2, BB), 512, SM_GEMM>>>(
        pAh2, pAl2, pBh + B_LAYER_OFF, pBl + B_LAYER_OFF, pd1, conv1_b, ns1, noise1,
        nullptr, nullptr, nullptr, out_h);

    rgb_kernel<<<BB * 64, 256>>>(rgb, rgb_w, rgb_b, out_h, out_rgb);
}